// round 9
// baseline (speedup 1.0000x reference)
#include <cuda_runtime.h>
#include <cuda_fp16.h>
#include <cstdint>
#include <cstddef>

#define NTOK 16384
#define DIM  2048
#define FFD  5632

// ---------------- scratch: static device globals (no allocation) ------------
__device__ __align__(1024) __half g_xp [(size_t)2 * NTOK * DIM];
__device__ __align__(1024) __half g_h  [(size_t)2 * NTOK * FFD];
__device__ __align__(1024) __half g_wgT[(size_t)2 * FFD * DIM];
__device__ __align__(1024) __half g_wuT[(size_t)2 * FFD * DIM];
__device__ __align__(1024) __half g_wdT[(size_t)2 * DIM * FFD];
__device__ int g_count[2];
__device__ int g_rowtok[2 * NTOK];

// ---------------- PTX helpers (compute_103-safe: no tcgen05) -----------------
__device__ __forceinline__ uint32_t smem_to_u32(const void* p) {
    uint32_t a;
    asm("{ .reg .u64 t; cvta.to.shared.u64 t, %1; cvt.u32.u64 %0, t; }"
        : "=r"(a) : "l"(p));
    return a;
}

__device__ __forceinline__ void ldsm_x4(uint32_t& r0, uint32_t& r1,
                                        uint32_t& r2, uint32_t& r3,
                                        uint32_t addr) {
    asm volatile("ldmatrix.sync.aligned.m8n8.x4.shared.b16 {%0,%1,%2,%3}, [%4];"
                 : "=r"(r0), "=r"(r1), "=r"(r2), "=r"(r3) : "r"(addr));
}

__device__ __forceinline__ void mma16816(float* c, const uint32_t* a,
                                         uint32_t b0, uint32_t b1) {
    asm volatile(
        "mma.sync.aligned.m16n8k16.row.col.f32.f16.f16.f32 "
        "{%0,%1,%2,%3}, {%4,%5,%6,%7}, {%8,%9}, {%0,%1,%2,%3};"
        : "+f"(c[0]), "+f"(c[1]), "+f"(c[2]), "+f"(c[3])
        : "r"(a[0]), "r"(a[1]), "r"(a[2]), "r"(a[3]), "r"(b0), "r"(b1));
}

__device__ __forceinline__ void cp16(uint32_t dst, const void* src) {
    asm volatile("cp.async.cg.shared.global [%0], [%1], 16;"
                 :: "r"(dst), "l"(src));
}
#define CP_COMMIT() asm volatile("cp.async.commit_group;" ::: "memory")
#define CP_WAIT1()  asm volatile("cp.async.wait_group 1;" ::: "memory")

__device__ __forceinline__ float silu(float x) {
    return x * __fdividef(1.0f, 1.0f + __expf(-x));
}

// ---------------- small kernels ----------------------------------------------
__global__ void zero_counters_kernel() {
    if (threadIdx.x < 2) g_count[threadIdx.x] = 0;
}

__global__ void route_gather_kernel(const float* __restrict__ x,
                                    const int* __restrict__ mask) {
    __shared__ int s_row;
    int t = blockIdx.x;
    if (threadIdx.x == 0) {
        int e = (mask[t] != 0) ? 1 : 0;
        int slot = atomicAdd(&g_count[e], 1);
        g_rowtok[e * NTOK + slot] = t;
        s_row = e * NTOK + slot;
    }
    __syncthreads();
    int row = s_row;
    const float4* src = reinterpret_cast<const float4*>(x + (size_t)t * DIM);
    __half2* dst = reinterpret_cast<__half2*>(g_xp + (size_t)row * DIM);
    for (int i = threadIdx.x; i < DIM / 4; i += blockDim.x) {
        float4 v = src[i];
        dst[2 * i + 0] = __floats2half2_rn(v.x, v.y);
        dst[2 * i + 1] = __floats2half2_rn(v.z, v.w);
    }
}

// transpose [R,C] fp32 -> [C,R] fp16 (per expert matrix)
__global__ void transpose_convert_kernel(const float* __restrict__ src,
                                         int which, int e, int R, int C) {
    __shared__ float tile[64][65];
    __half* base = (which == 0) ? g_wgT : (which == 1) ? g_wuT : g_wdT;
    const float* s = src + (size_t)e * R * C;
    __half* d = base + (size_t)e * R * C;
    int c0 = blockIdx.x * 64;
    int r0 = blockIdx.y * 64;
    for (int idx = threadIdx.x; idx < 64 * 64; idx += 256) {
        int r = idx >> 6, c = idx & 63;
        tile[r][c] = s[(size_t)(r0 + r) * C + c0 + c];
    }
    __syncthreads();
    for (int idx = threadIdx.x; idx < 64 * 64; idx += 256) {
        int dc = idx >> 6, dr = idx & 63;   // dst row = c0+dc, dst col = r0+dr
        d[(size_t)(c0 + dc) * R + r0 + dr] = __float2half(tile[dr][dc]);
    }
}

// ---------------- GEMM tiling ------------------------------------------------
// CTA tile 128(M) x 64(N), 8 warps (4 M x 2 N), warp tile 32x32.
// K-major fp16 operands, BK=32 per stage, 2-stage cp.async pipeline.
// SROW = 40 halves (32 + 8 skew) -> conflict-free ldmatrix.
#define BM   128
#define BN   64
#define BK   32
#define SROW 40

// ---------------- GEMM1: gate+up fused, h = silu(g)*u ------------------------
__global__ __launch_bounds__(256) void gemm1_kernel() {
    __shared__ __half sm[2][(BM + 2 * BN) * SROW];

    int tid = threadIdx.x, wid = tid >> 5, lane = tid & 31;
    int e = blockIdx.z, cnt = g_count[e];
    int m0 = blockIdx.x * BM;
    if (m0 >= cnt) return;
    int n0 = blockIdx.y * BN;
    int wm = wid & 3, wn = wid >> 2;

    const __half* Ab = g_xp  + (size_t)(e * NTOK + m0) * DIM;
    const __half* Bg = g_wgT + (size_t)e * FFD * DIM + (size_t)n0 * DIM;
    const __half* Bu = g_wuT + (size_t)e * FFD * DIM + (size_t)n0 * DIM;
    uint32_t sbase = smem_to_u32(sm);
    const int STAGE_B = (BM + 2 * BN) * SROW * 2;  // bytes per stage

    float cg[2][4][4] = {}, cu[2][4][4] = {};

    int gq = lane >> 3, lr = lane & 7;
    int aRow = wm * 32 + lr + (gq & 1) * 8;          // + mt*16
    int aCol = (gq >> 1) * 8;                        // halves, + ks*16
    int bRow = wn * 32 + lr + ((gq >> 1) & 1) * 8;   // + j*16
    int bCol = (gq & 1) * 8;

    // loader: 1024 x 16B chunks (A 512, Bg 256, Bu 256)
    auto issue = [&](int it, int buf) {
        uint32_t db = sbase + buf * STAGE_B;
        #pragma unroll
        for (int rep = 0; rep < 4; rep++) {
            int u = rep * 256 + tid;
            if (u < 512) {
                int r = u >> 2, c = u & 3;
                cp16(db + (uint32_t)(r * SROW + c * 8) * 2,
                     Ab + (size_t)r * DIM + it * BK + c * 8);
            } else if (u < 768) {
                int v = u - 512, r = v >> 2, c = v & 3;
                cp16(db + (uint32_t)((BM + r) * SROW + c * 8) * 2,
                     Bg + (size_t)r * DIM + it * BK + c * 8);
            } else {
                int v = u - 768, r = v >> 2, c = v & 3;
                cp16(db + (uint32_t)((BM + BN + r) * SROW + c * 8) * 2,
                     Bu + (size_t)r * DIM + it * BK + c * 8);
            }
        }
    };

    issue(0, 0);
    CP_COMMIT();

    const int KT = DIM / BK;  // 64
    for (int it = 0; it < KT; ++it) {
        int buf = it & 1;
        if (it + 1 < KT) issue(it + 1, buf ^ 1);
        CP_COMMIT();
        CP_WAIT1();
        __syncthreads();

        uint32_t s0 = sbase + buf * STAGE_B;
        #pragma unroll
        for (int ks = 0; ks < 2; ++ks) {
            uint32_t a[2][4], bg[2][4], bu[2][4];
            #pragma unroll
            for (int mt = 0; mt < 2; ++mt)
                ldsm_x4(a[mt][0], a[mt][1], a[mt][2], a[mt][3],
                        s0 + (uint32_t)((aRow + mt * 16) * SROW + ks * 16 + aCol) * 2);
            #pragma unroll
            for (int j = 0; j < 2; ++j) {
                ldsm_x4(bg[j][0], bg[j][1], bg[j][2], bg[j][3],
                        s0 + (uint32_t)((BM + bRow + j * 16) * SROW + ks * 16 + bCol) * 2);
                ldsm_x4(bu[j][0], bu[j][1], bu[j][2], bu[j][3],
                        s0 + (uint32_t)((BM + BN + bRow + j * 16) * SROW + ks * 16 + bCol) * 2);
            }
            #pragma unroll
            for (int mt = 0; mt < 2; ++mt)
                #pragma unroll
                for (int j = 0; j < 2; ++j) {
                    mma16816(cg[mt][j * 2 + 0], a[mt], bg[j][0], bg[j][1]);
                    mma16816(cg[mt][j * 2 + 1], a[mt], bg[j][2], bg[j][3]);
                    mma16816(cu[mt][j * 2 + 0], a[mt], bu[j][0], bu[j][1]);
                    mma16816(cu[mt][j * 2 + 1], a[mt], bu[j][2], bu[j][3]);
                }
        }
        __syncthreads();
    }

    // epilogue: h = silu(g)*u, fp16, coalesced half2 stores
    __half* hout = g_h + (size_t)(e * NTOK + m0) * FFD + n0;
    int rb = wm * 32 + (lane >> 2);
    int cb = wn * 32 + (lane & 3) * 2;
    #pragma unroll
    for (int mt = 0; mt < 2; ++mt)
        #pragma unroll
        for (int nt = 0; nt < 4; ++nt) {
            float* pg = cg[mt][nt];
            float* pu = cu[mt][nt];
            int r = rb + mt * 16, c = cb + nt * 8;
            *reinterpret_cast<__half2*>(hout + (size_t)r * FFD + c) =
                __floats2half2_rn(silu(pg[0]) * pu[0], silu(pg[1]) * pu[1]);
            *reinterpret_cast<__half2*>(hout + (size_t)(r + 8) * FFD + c) =
                __floats2half2_rn(silu(pg[2]) * pu[2], silu(pg[3]) * pu[3]);
        }
}

// ---------------- GEMM2: out = h @ WdT, scattered to token order -------------
__global__ __launch_bounds__(256) void gemm2_kernel(float* __restrict__ out) {
    __shared__ __half sm[2][(BM + BN) * SROW];
    __shared__ int srt[BM];

    int tid = threadIdx.x, wid = tid >> 5, lane = tid & 31;
    int e = blockIdx.z, cnt = g_count[e];
    int m0 = blockIdx.x * BM;
    if (m0 >= cnt) return;
    int n0 = blockIdx.y * BN;
    int wm = wid & 3, wn = wid >> 2;

    for (int i = tid; i < BM; i += 256) {
        int rr = m0 + i;
        srt[i] = (rr < cnt) ? g_rowtok[e * NTOK + rr] : -1;
    }

    const __half* Ab = g_h   + (size_t)(e * NTOK + m0) * FFD;
    const __half* Bb = g_wdT + (size_t)e * DIM * FFD + (size_t)n0 * FFD;
    uint32_t sbase = smem_to_u32(sm);
    const int STAGE_B = (BM + BN) * SROW * 2;

    float cc[2][4][4] = {};

    int gq = lane >> 3, lr = lane & 7;
    int aRow = wm * 32 + lr + (gq & 1) * 8;
    int aCol = (gq >> 1) * 8;
    int bRow = wn * 32 + lr + ((gq >> 1) & 1) * 8;
    int bCol = (gq & 1) * 8;

    // loader: 768 x 16B chunks (A 512, B 256)
    auto issue = [&](int it, int buf) {
        uint32_t db = sbase + buf * STAGE_B;
        #pragma unroll
        for (int rep = 0; rep < 3; rep++) {
            int u = rep * 256 + tid;
            if (u < 512) {
                int r = u >> 2, c = u & 3;
                cp16(db + (uint32_t)(r * SROW + c * 8) * 2,
                     Ab + (size_t)r * FFD + it * BK + c * 8);
            } else {
                int v = u - 512, r = v >> 2, c = v & 3;
                cp16(db + (uint32_t)((BM + r) * SROW + c * 8) * 2,
                     Bb + (size_t)r * FFD + it * BK + c * 8);
            }
        }
    };

    issue(0, 0);
    CP_COMMIT();

    const int KT = FFD / BK;  // 176
    for (int it = 0; it < KT; ++it) {
        int buf = it & 1;
        if (it + 1 < KT) issue(it + 1, buf ^ 1);
        CP_COMMIT();
        CP_WAIT1();
        __syncthreads();

        uint32_t s0 = sbase + buf * STAGE_B;
        #pragma unroll
        for (int ks = 0; ks < 2; ++ks) {
            uint32_t a[2][4], bb[2][4];
            #pragma unroll
            for (int mt = 0; mt < 2; ++mt)
                ldsm_x4(a[mt][0], a[mt][1], a[mt][2], a[mt][3],
                        s0 + (uint32_t)((aRow + mt * 16) * SROW + ks * 16 + aCol) * 2);
            #pragma unroll
            for (int j = 0; j < 2; ++j)
                ldsm_x4(bb[j][0], bb[j][1], bb[j][2], bb[j][3],
                        s0 + (uint32_t)((BM + bRow + j * 16) * SROW + ks * 16 + bCol) * 2);
            #pragma unroll
            for (int mt = 0; mt < 2; ++mt)
                #pragma unroll
                for (int j = 0; j < 2; ++j) {
                    mma16816(cc[mt][j * 2 + 0], a[mt], bb[j][0], bb[j][1]);
                    mma16816(cc[mt][j * 2 + 1], a[mt], bb[j][2], bb[j][3]);
                }
        }
        __syncthreads();
    }

    // epilogue: scatter rows back to original token positions (fp32)
    int rb = wm * 32 + (lane >> 2);
    int cb = n0 + wn * 32 + (lane & 3) * 2;
    #pragma unroll
    for (int mt = 0; mt < 2; ++mt)
        #pragma unroll
        for (int nt = 0; nt < 4; ++nt) {
            float* p = cc[mt][nt];
            int rl = rb + mt * 16;
            int c = cb + nt * 8;
            int t0 = srt[rl];
            if (t0 >= 0) {
                float2 v = make_float2(p[0], p[1]);
                *reinterpret_cast<float2*>(out + (size_t)t0 * DIM + c) = v;
            }
            int t1 = srt[rl + 8];
            if (t1 >= 0) {
                float2 v = make_float2(p[2], p[3]);
                *reinterpret_cast<float2*>(out + (size_t)t1 * DIM + c) = v;
            }
        }
}

// ---------------- launch ------------------------------------------------------
extern "C" void kernel_launch(void* const* d_in, const int* in_sizes, int n_in,
                              void* d_out, int out_size) {
    const float* hs   = (const float*)d_in[0];
    const int*   mask = (const int*)d_in[1];
    const float* wg   = (const float*)d_in[2];
    const float* wu   = (const float*)d_in[3];
    const float* wd   = (const float*)d_in[4];
    float* out = (float*)d_out;
    (void)in_sizes; (void)n_in; (void)out_size;

    zero_counters_kernel<<<1, 32>>>();
    route_gather_kernel<<<NTOK, 128>>>(hs, mask);

    // wg/wu: [D,FF] -> [FF,D] ; wd: [FF,D] -> [D,FF]
    dim3 tgu(FFD / 64, DIM / 64);
    dim3 tgd(DIM / 64, FFD / 64);
    transpose_convert_kernel<<<tgu, 256>>>(wg, 0, 0, DIM, FFD);
    transpose_convert_kernel<<<tgu, 256>>>(wg, 0, 1, DIM, FFD);
    transpose_convert_kernel<<<tgu, 256>>>(wu, 1, 0, DIM, FFD);
    transpose_convert_kernel<<<tgu, 256>>>(wu, 1, 1, DIM, FFD);
    transpose_convert_kernel<<<tgd, 256>>>(wd, 2, 0, FFD, DIM);
    transpose_convert_kernel<<<tgd, 256>>>(wd, 2, 1, FFD, DIM);

    // x = M-tiles fast: a wave of CTAs shares one N-tile's weights (L2 reuse)
    dim3 g1(NTOK / BM, FFD / BN, 2);
    gemm1_kernel<<<g1, 256>>>();

    dim3 g2(NTOK / BM, DIM / BN, 2);
    gemm2_kernel<<<g2, 256>>>(out);
}

// round 11
// speedup vs baseline: 1.0902x; 1.0902x over previous
#include <cuda_runtime.h>
#include <cuda_fp16.h>
#include <cstdint>
#include <cstddef>

#define NTOK 16384
#define DIM  2048
#define FFD  5632

// ---------------- scratch: static device globals (no allocation) ------------
__device__ __align__(1024) __half g_xp [(size_t)2 * NTOK * DIM];
__device__ __align__(1024) __half g_h  [(size_t)2 * NTOK * FFD];
__device__ __align__(1024) __half g_wgH[(size_t)2 * DIM * FFD];  // [D,FF] n-major
__device__ __align__(1024) __half g_wuH[(size_t)2 * DIM * FFD];  // [D,FF] n-major
__device__ __align__(1024) __half g_wdH[(size_t)2 * FFD * DIM];  // [FF,D] n-major
__device__ int g_count[2];
__device__ int g_rowtok[2 * NTOK];

// ---------------- PTX helpers (compute_103-safe: no tcgen05) -----------------
__device__ __forceinline__ uint32_t smem_to_u32(const void* p) {
    uint32_t a;
    asm("{ .reg .u64 t; cvta.to.shared.u64 t, %1; cvt.u32.u64 %0, t; }"
        : "=r"(a) : "l"(p));
    return a;
}

__device__ __forceinline__ void ldsm_x4(uint32_t& r0, uint32_t& r1,
                                        uint32_t& r2, uint32_t& r3,
                                        uint32_t addr) {
    asm volatile("ldmatrix.sync.aligned.m8n8.x4.shared.b16 {%0,%1,%2,%3}, [%4];"
                 : "=r"(r0), "=r"(r1), "=r"(r2), "=r"(r3) : "r"(addr));
}

// transposed load: n-major [K,N] smem tile -> K-major B fragments
__device__ __forceinline__ void ldsm_x4t(uint32_t& r0, uint32_t& r1,
                                         uint32_t& r2, uint32_t& r3,
                                         uint32_t addr) {
    asm volatile("ldmatrix.sync.aligned.m8n8.x4.trans.shared.b16 {%0,%1,%2,%3}, [%4];"
                 : "=r"(r0), "=r"(r1), "=r"(r2), "=r"(r3) : "r"(addr));
}

__device__ __forceinline__ void mma16816(float* c, const uint32_t* a,
                                         uint32_t b0, uint32_t b1) {
    asm volatile(
        "mma.sync.aligned.m16n8k16.row.col.f32.f16.f16.f32 "
        "{%0,%1,%2,%3}, {%4,%5,%6,%7}, {%8,%9}, {%0,%1,%2,%3};"
        : "+f"(c[0]), "+f"(c[1]), "+f"(c[2]), "+f"(c[3])
        : "r"(a[0]), "r"(a[1]), "r"(a[2]), "r"(a[3]), "r"(b0), "r"(b1));
}

__device__ __forceinline__ void cp16(uint32_t dst, const void* src) {
    asm volatile("cp.async.cg.shared.global [%0], [%1], 16;"
                 :: "r"(dst), "l"(src));
}
#define CP_COMMIT() asm volatile("cp.async.commit_group;" ::: "memory")
#define CP_WAIT1()  asm volatile("cp.async.wait_group 1;" ::: "memory")

__device__ __forceinline__ float silu(float x) {
    return x * __fdividef(1.0f, 1.0f + __expf(-x));
}

// supergroup swizzle: G=8 n-tiles, n-fast within group -> L2-resident wave
__device__ __forceinline__ void tilemap(int bx, int mtiles, int ntiles,
                                        int& m, int& n) {
    const int G = 8;
    int full = (ntiles / G) * G;
    if (bx < full * mtiles) {
        int per = G * mtiles;
        int sg = bx / per, rem = bx % per;
        n = sg * G + rem % G;
        m = rem / G;
    } else {
        int rem = bx - full * mtiles;
        int w = ntiles - full;
        n = full + rem % w;
        m = rem / w;
    }
}

// ---------------- small kernels ----------------------------------------------
__global__ void zero_counters_kernel() {
    if (threadIdx.x < 2) g_count[threadIdx.x] = 0;
}

__global__ void route_gather_kernel(const float* __restrict__ x,
                                    const int* __restrict__ mask) {
    __shared__ int s_row;
    int t = blockIdx.x;
    if (threadIdx.x == 0) {
        int e = (mask[t] != 0) ? 1 : 0;
        int slot = atomicAdd(&g_count[e], 1);
        g_rowtok[e * NTOK + slot] = t;
        s_row = e * NTOK + slot;
    }
    __syncthreads();
    int row = s_row;
    const float4* src = reinterpret_cast<const float4*>(x + (size_t)t * DIM);
    __half2* dst = reinterpret_cast<__half2*>(g_xp + (size_t)row * DIM);
    for (int i = threadIdx.x; i < DIM / 4; i += blockDim.x) {
        float4 v = src[i];
        dst[2 * i + 0] = __floats2half2_rn(v.x, v.y);
        dst[2 * i + 1] = __floats2half2_rn(v.z, v.w);
    }
}

// streaming fp32 -> fp16 convert (same layout), fully coalesced
__global__ void convert_kernel(const float* __restrict__ src,
                               __half* __restrict__ dst, int n4) {
    int stride = gridDim.x * blockDim.x;
    for (int i = blockIdx.x * blockDim.x + threadIdx.x; i < n4; i += stride) {
        float4 v = reinterpret_cast<const float4*>(src)[i];
        __half2* d = reinterpret_cast<__half2*>(dst) + 2 * (size_t)i;
        d[0] = __floats2half2_rn(v.x, v.y);
        d[1] = __floats2half2_rn(v.z, v.w);
    }
}

// ---------------- GEMM tiling ------------------------------------------------
// CTA tile 128(M) x 128(N), 8 warps (4M x 2N), warp tile 32x64.
// A: K-major smem rows (SRA=40 halves). B: n-major smem rows (SRB=136 halves),
// loaded with ldmatrix.trans. BK=32 per stage, 3-stage cp.async pipeline.
#define BM   128
#define BN   128
#define BK   32
#define SRA  40
#define SRB  136
#define STGA (BM * SRA)        // 5120 halves
#define STGB (BK * SRB)        // 4352 halves
#define STG1 (STGA + 2 * STGB) // gemm1 stage: 13824 halves = 27648 B
#define STG2 (STGA + STGB)     // gemm2 stage:  9472 halves = 18944 B
#define SMEM1 (3 * STG1 * 2)
#define SMEM2 (3 * STG2 * 2)

// ---------------- GEMM1: gate+up fused, h = silu(g)*u ------------------------
__global__ __launch_bounds__(256, 1) void gemm1_kernel() {
    extern __shared__ __half sm[];

    int tid = threadIdx.x, wid = tid >> 5, lane = tid & 31;
    int e = blockIdx.y, cnt = g_count[e];
    int mt_i, nt_i;
    tilemap(blockIdx.x, NTOK / BM, FFD / BN, mt_i, nt_i);
    int m0 = mt_i * BM;
    if (m0 >= cnt) return;
    int n0 = nt_i * BN;
    int wm = wid & 3, wn = wid >> 2;

    const __half* Ab = g_xp  + (size_t)(e * NTOK + m0) * DIM;
    const __half* Bg = g_wgH + (size_t)e * DIM * FFD + n0;
    const __half* Bu = g_wuH + (size_t)e * DIM * FFD + n0;
    uint32_t sbase = smem_to_u32(sm);

    float cg[2][8][4] = {}, cu[2][8][4] = {};

    int gq = lane >> 3, lr = lane & 7;
    int aRow = wm * 32 + lr + (gq & 1) * 8;            // + mt*16
    int aCol = (gq >> 1) * 8;                          // + ks*16
    uint32_t aoff = (uint32_t)(aRow * SRA + aCol) * 2;
    int bR = lr + (gq & 1) * 8;                        // k row, + ks*16
    int bC = wn * 64 + ((gq >> 1) & 1) * 8;            // n col, + j*16
    uint32_t boff = (uint32_t)(bR * SRB + bC) * 2;

    auto issue = [&](int it, int s) {
        uint32_t db = sbase + (uint32_t)(s * STG1) * 2;
        const __half* As = Ab + it * BK;
        const __half* Gs = Bg + (size_t)(it * BK) * FFD;
        const __half* Us = Bu + (size_t)(it * BK) * FFD;
        #pragma unroll
        for (int rep = 0; rep < 6; rep++) {
            int u = rep * 256 + tid;
            if (u < 512) {
                int r = u >> 2, c = u & 3;
                cp16(db + (uint32_t)(r * SRA + c * 8) * 2,
                     As + (size_t)r * DIM + c * 8);
            } else if (u < 1024) {
                int v = u - 512, r = v >> 4, c = v & 15;
                cp16(db + (uint32_t)(STGA + r * SRB + c * 8) * 2,
                     Gs + (size_t)r * FFD + c * 8);
            } else {
                int v = u - 1024, r = v >> 4, c = v & 15;
                cp16(db + (uint32_t)(STGA + STGB + r * SRB + c * 8) * 2,
                     Us + (size_t)r * FFD + c * 8);
            }
        }
    };

    issue(0, 0); CP_COMMIT();
    issue(1, 1); CP_COMMIT();

    const int KT = DIM / BK;  // 64
    for (int it = 0; it < KT; ++it) {
        CP_WAIT1();
        __syncthreads();
        if (it + 2 < KT) issue(it + 2, (it + 2) % 3);
        CP_COMMIT();

        uint32_t s0 = sbase + (uint32_t)((it % 3) * STG1) * 2;
        #pragma unroll
        for (int ks = 0; ks < 2; ++ks) {
            uint32_t a[2][4], b[4][4];
            #pragma unroll
            for (int mt = 0; mt < 2; ++mt)
                ldsm_x4(a[mt][0], a[mt][1], a[mt][2], a[mt][3],
                        s0 + aoff + (uint32_t)(mt * 16 * SRA + ks * 16) * 2);
            // gate
            uint32_t gb = s0 + (uint32_t)(STGA + ks * 16 * SRB) * 2 + boff;
            #pragma unroll
            for (int j = 0; j < 4; ++j)
                ldsm_x4t(b[j][0], b[j][1], b[j][2], b[j][3], gb + j * 32);
            #pragma unroll
            for (int mt = 0; mt < 2; ++mt)
                #pragma unroll
                for (int j = 0; j < 4; ++j) {
                    mma16816(cg[mt][j * 2 + 0], a[mt], b[j][0], b[j][1]);
                    mma16816(cg[mt][j * 2 + 1], a[mt], b[j][2], b[j][3]);
                }
            // up
            uint32_t ub = gb + (uint32_t)STGB * 2;
            #pragma unroll
            for (int j = 0; j < 4; ++j)
                ldsm_x4t(b[j][0], b[j][1], b[j][2], b[j][3], ub + j * 32);
            #pragma unroll
            for (int mt = 0; mt < 2; ++mt)
                #pragma unroll
                for (int j = 0; j < 4; ++j) {
                    mma16816(cu[mt][j * 2 + 0], a[mt], b[j][0], b[j][1]);
                    mma16816(cu[mt][j * 2 + 1], a[mt], b[j][2], b[j][3]);
                }
        }
    }

    // epilogue: h = silu(g)*u, fp16 half2 stores
    __half* hout = g_h + (size_t)(e * NTOK + m0) * FFD + n0;
    int rb = wm * 32 + (lane >> 2);
    int cb = wn * 64 + (lane & 3) * 2;
    #pragma unroll
    for (int mt = 0; mt < 2; ++mt)
        #pragma unroll
        for (int nt = 0; nt < 8; ++nt) {
            float* pg = cg[mt][nt];
            float* pu = cu[mt][nt];
            int r = rb + mt * 16, c = cb + nt * 8;
            *reinterpret_cast<__half2*>(hout + (size_t)r * FFD + c) =
                __floats2half2_rn(silu(pg[0]) * pu[0], silu(pg[1]) * pu[1]);
            *reinterpret_cast<__half2*>(hout + (size_t)(r + 8) * FFD + c) =
                __floats2half2_rn(silu(pg[2]) * pu[2], silu(pg[3]) * pu[3]);
        }
}

// ---------------- GEMM2: out = h @ Wd, scattered to token order --------------
__global__ __launch_bounds__(256, 2) void gemm2_kernel(float* __restrict__ out) {
    extern __shared__ __half sm[];
    __shared__ int srt[BM];

    int tid = threadIdx.x, wid = tid >> 5, lane = tid & 31;
    int e = blockIdx.y, cnt = g_count[e];
    int mt_i, nt_i;
    tilemap(blockIdx.x, NTOK / BM, DIM / BN, mt_i, nt_i);
    int m0 = mt_i * BM;
    if (m0 >= cnt) return;
    int n0 = nt_i * BN;
    int wm = wid & 3, wn = wid >> 2;

    for (int i = tid; i < BM; i += 256) {
        int rr = m0 + i;
        srt[i] = (rr < cnt) ? g_rowtok[e * NTOK + rr] : -1;
    }

    const __half* Ab = g_h   + (size_t)(e * NTOK + m0) * FFD;
    const __half* Bb = g_wdH + (size_t)e * FFD * DIM + n0;
    uint32_t sbase = smem_to_u32(sm);

    float cc[2][8][4] = {};

    int gq = lane >> 3, lr = lane & 7;
    int aRow = wm * 32 + lr + (gq & 1) * 8;
    int aCol = (gq >> 1) * 8;
    uint32_t aoff = (uint32_t)(aRow * SRA + aCol) * 2;
    int bR = lr + (gq & 1) * 8;
    int bC = wn * 64 + ((gq >> 1) & 1) * 8;
    uint32_t boff = (uint32_t)(bR * SRB + bC) * 2;

    auto issue = [&](int it, int s) {
        uint32_t db = sbase + (uint32_t)(s * STG2) * 2;
        const __half* As = Ab + it * BK;
        const __half* Bs = Bb + (size_t)(it * BK) * DIM;
        #pragma unroll
        for (int rep = 0; rep < 4; rep++) {
            int u = rep * 256 + tid;
            if (u < 512) {
                int r = u >> 2, c = u & 3;
                cp16(db + (uint32_t)(r * SRA + c * 8) * 2,
                     As + (size_t)r * FFD + c * 8);
            } else {
                int v = u - 512, r = v >> 4, c = v & 15;
                cp16(db + (uint32_t)(STGA + r * SRB + c * 8) * 2,
                     Bs + (size_t)r * DIM + c * 8);
            }
        }
    };

    issue(0, 0); CP_COMMIT();
    issue(1, 1); CP_COMMIT();

    const int KT = FFD / BK;  // 176
    for (int it = 0; it < KT; ++it) {
        CP_WAIT1();
        __syncthreads();
        if (it + 2 < KT) issue(it + 2, (it + 2) % 3);
        CP_COMMIT();

        uint32_t s0 = sbase + (uint32_t)((it % 3) * STG2) * 2;
        #pragma unroll
        for (int ks = 0; ks < 2; ++ks) {
            uint32_t a[2][4], b[4][4];
            #pragma unroll
            for (int mt = 0; mt < 2; ++mt)
                ldsm_x4(a[mt][0], a[mt][1], a[mt][2], a[mt][3],
                        s0 + aoff + (uint32_t)(mt * 16 * SRA + ks * 16) * 2);
            uint32_t bb = s0 + (uint32_t)(STGA + ks * 16 * SRB) * 2 + boff;
            #pragma unroll
            for (int j = 0; j < 4; ++j)
                ldsm_x4t(b[j][0], b[j][1], b[j][2], b[j][3], bb + j * 32);
            #pragma unroll
            for (int mt = 0; mt < 2; ++mt)
                #pragma unroll
                for (int j = 0; j < 4; ++j) {
                    mma16816(cc[mt][j * 2 + 0], a[mt], b[j][0], b[j][1]);
                    mma16816(cc[mt][j * 2 + 1], a[mt], b[j][2], b[j][3]);
                }
        }
    }

    // epilogue: scatter rows to original token positions (fp32 float2)
    int rb = wm * 32 + (lane >> 2);
    int cb = n0 + wn * 64 + (lane & 3) * 2;
    #pragma unroll
    for (int mt = 0; mt < 2; ++mt)
        #pragma unroll
        for (int nt = 0; nt < 8; ++nt) {
            float* p = cc[mt][nt];
            int rl = rb + mt * 16;
            int c = cb + nt * 8;
            int t0 = srt[rl];
            if (t0 >= 0)
                *reinterpret_cast<float2*>(out + (size_t)t0 * DIM + c) =
                    make_float2(p[0], p[1]);
            int t1 = srt[rl + 8];
            if (t1 >= 0)
                *reinterpret_cast<float2*>(out + (size_t)t1 * DIM + c) =
                    make_float2(p[2], p[3]);
        }
}

// ---------------- launch ------------------------------------------------------
extern "C" void kernel_launch(void* const* d_in, const int* in_sizes, int n_in,
                              void* d_out, int out_size) {
    const float* hs   = (const float*)d_in[0];
    const int*   mask = (const int*)d_in[1];
    const float* wg   = (const float*)d_in[2];
    const float* wu   = (const float*)d_in[3];
    const float* wd   = (const float*)d_in[4];
    float* out = (float*)d_out;
    (void)in_sizes; (void)n_in; (void)out_size;

    cudaFuncSetAttribute(gemm1_kernel,
                         cudaFuncAttributeMaxDynamicSharedMemorySize, SMEM1);
    cudaFuncSetAttribute(gemm2_kernel,
                         cudaFuncAttributeMaxDynamicSharedMemorySize, SMEM2);

    zero_counters_kernel<<<1, 32>>>();
    route_gather_kernel<<<NTOK, 128>>>(hs, mask);

    __half* wgH; __half* wuH; __half* wdH;
    cudaGetSymbolAddress((void**)&wgH, g_wgH);
    cudaGetSymbolAddress((void**)&wuH, g_wuH);
    cudaGetSymbolAddress((void**)&wdH, g_wdH);
    const int NW4 = 2 * DIM * FFD / 4;
    convert_kernel<<<4096, 256>>>(wg, wgH, NW4);
    convert_kernel<<<4096, 256>>>(wu, wuH, NW4);
    convert_kernel<<<4096, 256>>>(wd, wdH, NW4);

    dim3 g1((NTOK / BM) * (FFD / BN), 2);
    gemm1_kernel<<<g1, 256, SMEM1>>>();

    dim3 g2((NTOK / BM) * (DIM / BN), 2);
    gemm2_kernel<<<g2, 256, SMEM2>>>(out);
}

// round 12
// speedup vs baseline: 1.2699x; 1.1649x over previous
#include <cuda_runtime.h>
#include <cuda_fp16.h>
#include <cstdint>
#include <cstddef>

#define NTOK 16384
#define DIM  2048
#define FFD  5632

// ---------------- scratch: static device globals (no allocation) ------------
__device__ __align__(1024) __half g_xp [(size_t)2 * NTOK * DIM];
__device__ __align__(1024) __half g_h  [(size_t)2 * NTOK * FFD];
__device__ __align__(1024) __half g_wgH[(size_t)2 * DIM * FFD];  // [D,FF] n-major
__device__ __align__(1024) __half g_wuH[(size_t)2 * DIM * FFD];  // [D,FF] n-major
__device__ __align__(1024) __half g_wdH[(size_t)2 * FFD * DIM];  // [FF,D] n-major
__device__ int g_count[2];
__device__ int g_rowtok[2 * NTOK];

// ---------------- PTX helpers (compute_103-safe: no tcgen05) -----------------
__device__ __forceinline__ uint32_t smem_to_u32(const void* p) {
    uint32_t a;
    asm("{ .reg .u64 t; cvta.to.shared.u64 t, %1; cvt.u32.u64 %0, t; }"
        : "=r"(a) : "l"(p));
    return a;
}

__device__ __forceinline__ void ldsm_x4(uint32_t& r0, uint32_t& r1,
                                        uint32_t& r2, uint32_t& r3,
                                        uint32_t addr) {
    asm volatile("ldmatrix.sync.aligned.m8n8.x4.shared.b16 {%0,%1,%2,%3}, [%4];"
                 : "=r"(r0), "=r"(r1), "=r"(r2), "=r"(r3) : "r"(addr));
}

// transposed load: n-major [K,N] smem tile -> K-major B fragments
__device__ __forceinline__ void ldsm_x4t(uint32_t& r0, uint32_t& r1,
                                         uint32_t& r2, uint32_t& r3,
                                         uint32_t addr) {
    asm volatile("ldmatrix.sync.aligned.m8n8.x4.trans.shared.b16 {%0,%1,%2,%3}, [%4];"
                 : "=r"(r0), "=r"(r1), "=r"(r2), "=r"(r3) : "r"(addr));
}

__device__ __forceinline__ void mma16816(float* c, const uint32_t* a,
                                         uint32_t b0, uint32_t b1) {
    asm volatile(
        "mma.sync.aligned.m16n8k16.row.col.f32.f16.f16.f32 "
        "{%0,%1,%2,%3}, {%4,%5,%6,%7}, {%8,%9}, {%0,%1,%2,%3};"
        : "+f"(c[0]), "+f"(c[1]), "+f"(c[2]), "+f"(c[3])
        : "r"(a[0]), "r"(a[1]), "r"(a[2]), "r"(a[3]), "r"(b0), "r"(b1));
}

__device__ __forceinline__ void cp16(uint32_t dst, const void* src) {
    asm volatile("cp.async.cg.shared.global [%0], [%1], 16;"
                 :: "r"(dst), "l"(src));
}
#define CP_COMMIT() asm volatile("cp.async.commit_group;" ::: "memory")
#define CP_WAIT1()  asm volatile("cp.async.wait_group 1;" ::: "memory")

__device__ __forceinline__ float silu(float x) {
    return x * __fdividef(1.0f, 1.0f + __expf(-x));
}

// supergroup swizzle: G=8 n-tiles, n-fast within group -> L2-resident wave
__device__ __forceinline__ void tilemap(int bx, int mtiles, int ntiles,
                                        int& m, int& n) {
    const int G = 8;
    int full = (ntiles / G) * G;
    if (bx < full * mtiles) {
        int per = G * mtiles;
        int sg = bx / per, rem = bx % per;
        n = sg * G + rem % G;
        m = rem / G;
    } else {
        int rem = bx - full * mtiles;
        int w = ntiles - full;
        n = full + rem % w;
        m = rem / w;
    }
}

// ---------------- small kernels ----------------------------------------------
__global__ void zero_counters_kernel() {
    if (threadIdx.x < 2) g_count[threadIdx.x] = 0;
}

__global__ void route_gather_kernel(const float* __restrict__ x,
                                    const int* __restrict__ mask) {
    __shared__ int s_row;
    int t = blockIdx.x;
    if (threadIdx.x == 0) {
        int e = (mask[t] != 0) ? 1 : 0;
        int slot = atomicAdd(&g_count[e], 1);
        g_rowtok[e * NTOK + slot] = t;
        s_row = e * NTOK + slot;
    }
    __syncthreads();
    int row = s_row;
    const float4* src = reinterpret_cast<const float4*>(x + (size_t)t * DIM);
    __half2* dst = reinterpret_cast<__half2*>(g_xp + (size_t)row * DIM);
    for (int i = threadIdx.x; i < DIM / 4; i += blockDim.x) {
        float4 v = src[i];
        dst[2 * i + 0] = __floats2half2_rn(v.x, v.y);
        dst[2 * i + 1] = __floats2half2_rn(v.z, v.w);
    }
}

// streaming fp32 -> fp16 convert (same layout), fully coalesced
__global__ void convert_kernel(const float* __restrict__ src,
                               __half* __restrict__ dst, int n4) {
    int stride = gridDim.x * blockDim.x;
    for (int i = blockIdx.x * blockDim.x + threadIdx.x; i < n4; i += stride) {
        float4 v = reinterpret_cast<const float4*>(src)[i];
        __half2* d = reinterpret_cast<__half2*>(dst) + 2 * (size_t)i;
        d[0] = __floats2half2_rn(v.x, v.y);
        d[1] = __floats2half2_rn(v.z, v.w);
    }
}

// ---------------- GEMM tiling ------------------------------------------------
// CTA tile 128(M) x 128(N), 8 warps (4M x 2N), warp tile 32x64.
// A: K-major smem rows (SRA=72 halves for BK=64). B: n-major smem rows
// (SRB=136 halves), ldmatrix.trans. BK=64 per stage, 3-stage cp.async pipe.
#define BM   128
#define BN   128
#define BK   64
#define SRA  72
#define SRB  136
#define STGA (BM * SRA)        // 9216 halves
#define STGB (BK * SRB)        // 8704 halves
#define STG1 (STGA + 2 * STGB) // gemm1 stage: 26624 halves = 53248 B
#define STG2 (STGA + STGB)     // gemm2 stage: 17920 halves = 35840 B
#define SMEM1 (3 * STG1 * 2)   // 159744 B
#define SMEM2 (3 * STG2 * 2)   // 107520 B

// ---------------- GEMM1: gate+up fused, h = silu(g)*u ------------------------
__global__ __launch_bounds__(256, 1) void gemm1_kernel() {
    extern __shared__ __half sm[];

    int tid = threadIdx.x, wid = tid >> 5, lane = tid & 31;
    int e = blockIdx.y, cnt = g_count[e];
    int mt_i, nt_i;
    tilemap(blockIdx.x, NTOK / BM, FFD / BN, mt_i, nt_i);
    int m0 = mt_i * BM;
    if (m0 >= cnt) return;
    int n0 = nt_i * BN;
    int wm = wid & 3, wn = wid >> 2;

    const __half* Ab = g_xp  + (size_t)(e * NTOK + m0) * DIM;
    const __half* Bg = g_wgH + (size_t)e * DIM * FFD + n0;
    const __half* Bu = g_wuH + (size_t)e * DIM * FFD + n0;
    uint32_t sbase = smem_to_u32(sm);

    float cg[2][8][4] = {}, cu[2][8][4] = {};

    int gq = lane >> 3, lr = lane & 7;
    int aRow = wm * 32 + lr + (gq & 1) * 8;            // + mt*16
    int aCol = (gq >> 1) * 8;                          // + ks*16
    uint32_t aoff = (uint32_t)(aRow * SRA + aCol) * 2;
    int bR = lr + (gq & 1) * 8;                        // k row, + ks*16
    int bC = wn * 64 + ((gq >> 1) & 1) * 8;            // n col, + j*16
    uint32_t boff = (uint32_t)(bR * SRB + bC) * 2;

    // loader: 3072 x 16B chunks (A 1024, Bg 1024, Bu 1024)
    auto issue = [&](int it, int s) {
        uint32_t db = sbase + (uint32_t)(s * STG1) * 2;
        const __half* As = Ab + it * BK;
        const __half* Gs = Bg + (size_t)(it * BK) * FFD;
        const __half* Us = Bu + (size_t)(it * BK) * FFD;
        #pragma unroll
        for (int rep = 0; rep < 12; rep++) {
            int u = rep * 256 + tid;
            if (u < 1024) {
                int r = u >> 3, c = u & 7;
                cp16(db + (uint32_t)(r * SRA + c * 8) * 2,
                     As + (size_t)r * DIM + c * 8);
            } else if (u < 2048) {
                int v = u - 1024, r = v >> 4, c = v & 15;
                cp16(db + (uint32_t)(STGA + r * SRB + c * 8) * 2,
                     Gs + (size_t)r * FFD + c * 8);
            } else {
                int v = u - 2048, r = v >> 4, c = v & 15;
                cp16(db + (uint32_t)(STGA + STGB + r * SRB + c * 8) * 2,
                     Us + (size_t)r * FFD + c * 8);
            }
        }
    };

    issue(0, 0); CP_COMMIT();
    issue(1, 1); CP_COMMIT();

    const int KT = DIM / BK;  // 32
    for (int it = 0; it < KT; ++it) {
        CP_WAIT1();
        __syncthreads();
        if (it + 2 < KT) issue(it + 2, (it + 2) % 3);
        CP_COMMIT();

        uint32_t s0 = sbase + (uint32_t)((it % 3) * STG1) * 2;
        #pragma unroll
        for (int ks = 0; ks < 4; ++ks) {
            uint32_t a[2][4], b[4][4];
            #pragma unroll
            for (int mt = 0; mt < 2; ++mt)
                ldsm_x4(a[mt][0], a[mt][1], a[mt][2], a[mt][3],
                        s0 + aoff + (uint32_t)(mt * 16 * SRA + ks * 16) * 2);
            // gate
            uint32_t gb = s0 + (uint32_t)(STGA + ks * 16 * SRB) * 2 + boff;
            #pragma unroll
            for (int j = 0; j < 4; ++j)
                ldsm_x4t(b[j][0], b[j][1], b[j][2], b[j][3], gb + j * 32);
            #pragma unroll
            for (int mt = 0; mt < 2; ++mt)
                #pragma unroll
                for (int j = 0; j < 4; ++j) {
                    mma16816(cg[mt][j * 2 + 0], a[mt], b[j][0], b[j][1]);
                    mma16816(cg[mt][j * 2 + 1], a[mt], b[j][2], b[j][3]);
                }
            // up
            uint32_t ub = gb + (uint32_t)STGB * 2;
            #pragma unroll
            for (int j = 0; j < 4; ++j)
                ldsm_x4t(b[j][0], b[j][1], b[j][2], b[j][3], ub + j * 32);
            #pragma unroll
            for (int mt = 0; mt < 2; ++mt)
                #pragma unroll
                for (int j = 0; j < 4; ++j) {
                    mma16816(cu[mt][j * 2 + 0], a[mt], b[j][0], b[j][1]);
                    mma16816(cu[mt][j * 2 + 1], a[mt], b[j][2], b[j][3]);
                }
        }
    }

    // epilogue: h = silu(g)*u, fp16 half2 stores
    __half* hout = g_h + (size_t)(e * NTOK + m0) * FFD + n0;
    int rb = wm * 32 + (lane >> 2);
    int cb = wn * 64 + (lane & 3) * 2;
    #pragma unroll
    for (int mt = 0; mt < 2; ++mt)
        #pragma unroll
        for (int nt = 0; nt < 8; ++nt) {
            float* pg = cg[mt][nt];
            float* pu = cu[mt][nt];
            int r = rb + mt * 16, c = cb + nt * 8;
            *reinterpret_cast<__half2*>(hout + (size_t)r * FFD + c) =
                __floats2half2_rn(silu(pg[0]) * pu[0], silu(pg[1]) * pu[1]);
            *reinterpret_cast<__half2*>(hout + (size_t)(r + 8) * FFD + c) =
                __floats2half2_rn(silu(pg[2]) * pu[2], silu(pg[3]) * pu[3]);
        }
}

// ---------------- GEMM2: out = h @ Wd, scattered to token order --------------
__global__ __launch_bounds__(256, 2) void gemm2_kernel(float* __restrict__ out) {
    extern __shared__ __half sm[];
    __shared__ int srt[BM];

    int tid = threadIdx.x, wid = tid >> 5, lane = tid & 31;
    int e = blockIdx.y, cnt = g_count[e];
    int mt_i, nt_i;
    tilemap(blockIdx.x, NTOK / BM, DIM / BN, mt_i, nt_i);
    int m0 = mt_i * BM;
    if (m0 >= cnt) return;
    int n0 = nt_i * BN;
    int wm = wid & 3, wn = wid >> 2;

    for (int i = tid; i < BM; i += 256) {
        int rr = m0 + i;
        srt[i] = (rr < cnt) ? g_rowtok[e * NTOK + rr] : -1;
    }

    const __half* Ab = g_h   + (size_t)(e * NTOK + m0) * FFD;
    const __half* Bb = g_wdH + (size_t)e * FFD * DIM + n0;
    uint32_t sbase = smem_to_u32(sm);

    float cc[2][8][4] = {};

    int gq = lane >> 3, lr = lane & 7;
    int aRow = wm * 32 + lr + (gq & 1) * 8;
    int aCol = (gq >> 1) * 8;
    uint32_t aoff = (uint32_t)(aRow * SRA + aCol) * 2;
    int bR = lr + (gq & 1) * 8;
    int bC = wn * 64 + ((gq >> 1) & 1) * 8;
    uint32_t boff = (uint32_t)(bR * SRB + bC) * 2;

    // loader: 2048 x 16B chunks (A 1024, B 1024)
    auto issue = [&](int it, int s) {
        uint32_t db = sbase + (uint32_t)(s * STG2) * 2;
        const __half* As = Ab + it * BK;
        const __half* Bs = Bb + (size_t)(it * BK) * DIM;
        #pragma unroll
        for (int rep = 0; rep < 8; rep++) {
            int u = rep * 256 + tid;
            if (u < 1024) {
                int r = u >> 3, c = u & 7;
                cp16(db + (uint32_t)(r * SRA + c * 8) * 2,
                     As + (size_t)r * FFD + c * 8);
            } else {
                int v = u - 1024, r = v >> 4, c = v & 15;
                cp16(db + (uint32_t)(STGA + r * SRB + c * 8) * 2,
                     Bs + (size_t)r * DIM + c * 8);
            }
        }
    };

    issue(0, 0); CP_COMMIT();
    issue(1, 1); CP_COMMIT();

    const int KT = FFD / BK;  // 88
    for (int it = 0; it < KT; ++it) {
        CP_WAIT1();
        __syncthreads();
        if (it + 2 < KT) issue(it + 2, (it + 2) % 3);
        CP_COMMIT();

        uint32_t s0 = sbase + (uint32_t)((it % 3) * STG2) * 2;
        #pragma unroll
        for (int ks = 0; ks < 4; ++ks) {
            uint32_t a[2][4], b[4][4];
            #pragma unroll
            for (int mt = 0; mt < 2; ++mt)
                ldsm_x4(a[mt][0], a[mt][1], a[mt][2], a[mt][3],
                        s0 + aoff + (uint32_t)(mt * 16 * SRA + ks * 16) * 2);
            uint32_t bb = s0 + (uint32_t)(STGA + ks * 16 * SRB) * 2 + boff;
            #pragma unroll
            for (int j = 0; j < 4; ++j)
                ldsm_x4t(b[j][0], b[j][1], b[j][2], b[j][3], bb + j * 32);
            #pragma unroll
            for (int mt = 0; mt < 2; ++mt)
                #pragma unroll
                for (int j = 0; j < 4; ++j) {
                    mma16816(cc[mt][j * 2 + 0], a[mt], b[j][0], b[j][1]);
                    mma16816(cc[mt][j * 2 + 1], a[mt], b[j][2], b[j][3]);
                }
        }
    }

    // epilogue: scatter rows to original token positions (fp32 float2)
    int rb = wm * 32 + (lane >> 2);
    int cb = n0 + wn * 64 + (lane & 3) * 2;
    #pragma unroll
    for (int mt = 0; mt < 2; ++mt)
        #pragma unroll
        for (int nt = 0; nt < 8; ++nt) {
            float* p = cc[mt][nt];
            int rl = rb + mt * 16;
            int c = cb + nt * 8;
            int t0 = srt[rl];
            if (t0 >= 0)
                *reinterpret_cast<float2*>(out + (size_t)t0 * DIM + c) =
                    make_float2(p[0], p[1]);
            int t1 = srt[rl + 8];
            if (t1 >= 0)
                *reinterpret_cast<float2*>(out + (size_t)t1 * DIM + c) =
                    make_float2(p[2], p[3]);
        }
}

// ---------------- launch ------------------------------------------------------
extern "C" void kernel_launch(void* const* d_in, const int* in_sizes, int n_in,
                              void* d_out, int out_size) {
    const float* hs   = (const float*)d_in[0];
    const int*   mask = (const int*)d_in[1];
    const float* wg   = (const float*)d_in[2];
    const float* wu   = (const float*)d_in[3];
    const float* wd   = (const float*)d_in[4];
    float* out = (float*)d_out;
    (void)in_sizes; (void)n_in; (void)out_size;

    cudaFuncSetAttribute(gemm1_kernel,
                         cudaFuncAttributeMaxDynamicSharedMemorySize, SMEM1);
    cudaFuncSetAttribute(gemm2_kernel,
                         cudaFuncAttributeMaxDynamicSharedMemorySize, SMEM2);

    zero_counters_kernel<<<1, 32>>>();
    route_gather_kernel<<<NTOK, 128>>>(hs, mask);

    __half* wgH; __half* wuH; __half* wdH;
    cudaGetSymbolAddress((void**)&wgH, g_wgH);
    cudaGetSymbolAddress((void**)&wuH, g_wuH);
    cudaGetSymbolAddress((void**)&wdH, g_wdH);
    const int NW4 = 2 * DIM * FFD / 4;
    convert_kernel<<<4096, 256>>>(wg, wgH, NW4);
    convert_kernel<<<4096, 256>>>(wu, wuH, NW4);
    convert_kernel<<<4096, 256>>>(wd, wdH, NW4);

    dim3 g1((NTOK / BM) * (FFD / BN), 2);
    gemm1_kernel<<<g1, 256, SMEM1>>>();

    dim3 g2((NTOK / BM) * (DIM / BN), 2);
    gemm2_kernel<<<g2, 256, SMEM2>>>(out);
}

// round 13
// speedup vs baseline: 1.2928x; 1.0180x over previous
#include <cuda_runtime.h>
#include <cuda_fp16.h>
#include <cstdint>
#include <cstddef>

#define NTOK 16384
#define DIM  2048
#define FFD  5632

// ---------------- scratch: static device globals (no allocation) ------------
__device__ __align__(1024) __half g_xp [(size_t)2 * NTOK * DIM];
__device__ __align__(1024) __half g_h  [(size_t)2 * NTOK * FFD];
__device__ __align__(1024) __half g_wgH[(size_t)2 * DIM * FFD];  // [D,FF] n-major
__device__ __align__(1024) __half g_wuH[(size_t)2 * DIM * FFD];  // [D,FF] n-major
__device__ __align__(1024) __half g_wdH[(size_t)2 * FFD * DIM];  // [FF,D] n-major
__device__ int g_count[2];
__device__ int g_rowtok[2 * NTOK];

// ---------------- PTX helpers (compute_103-safe: no tcgen05) -----------------
__device__ __forceinline__ uint32_t smem_to_u32(const void* p) {
    uint32_t a;
    asm("{ .reg .u64 t; cvta.to.shared.u64 t, %1; cvt.u32.u64 %0, t; }"
        : "=r"(a) : "l"(p));
    return a;
}

__device__ __forceinline__ void ldsm_x4(uint32_t& r0, uint32_t& r1,
                                        uint32_t& r2, uint32_t& r3,
                                        uint32_t addr) {
    asm volatile("ldmatrix.sync.aligned.m8n8.x4.shared.b16 {%0,%1,%2,%3}, [%4];"
                 : "=r"(r0), "=r"(r1), "=r"(r2), "=r"(r3) : "r"(addr));
}

// transposed load: n-major [K,N] smem tile -> K-major B fragments
__device__ __forceinline__ void ldsm_x4t(uint32_t& r0, uint32_t& r1,
                                         uint32_t& r2, uint32_t& r3,
                                         uint32_t addr) {
    asm volatile("ldmatrix.sync.aligned.m8n8.x4.trans.shared.b16 {%0,%1,%2,%3}, [%4];"
                 : "=r"(r0), "=r"(r1), "=r"(r2), "=r"(r3) : "r"(addr));
}

__device__ __forceinline__ void mma16816(float* c, const uint32_t* a,
                                         uint32_t b0, uint32_t b1) {
    asm volatile(
        "mma.sync.aligned.m16n8k16.row.col.f32.f16.f16.f32 "
        "{%0,%1,%2,%3}, {%4,%5,%6,%7}, {%8,%9}, {%0,%1,%2,%3};"
        : "+f"(c[0]), "+f"(c[1]), "+f"(c[2]), "+f"(c[3])
        : "r"(a[0]), "r"(a[1]), "r"(a[2]), "r"(a[3]), "r"(b0), "r"(b1));
}

__device__ __forceinline__ void cp16(uint32_t dst, const void* src) {
    asm volatile("cp.async.cg.shared.global [%0], [%1], 16;"
                 :: "r"(dst), "l"(src));
}
#define CP_COMMIT() asm volatile("cp.async.commit_group;" ::: "memory")
#define CP_WAIT1()  asm volatile("cp.async.wait_group 1;" ::: "memory")

__device__ __forceinline__ float silu(float x) {
    return x * __fdividef(1.0f, 1.0f + __expf(-x));
}

// supergroup swizzle: G=8 n-tiles, n-fast within group -> L2-resident wave
__device__ __forceinline__ void tilemap(int bx, int mtiles, int ntiles,
                                        int& m, int& n) {
    const int G = 8;
    int full = (ntiles / G) * G;
    if (bx < full * mtiles) {
        int per = G * mtiles;
        int sg = bx / per, rem = bx % per;
        n = sg * G + rem % G;
        m = rem / G;
    } else {
        int rem = bx - full * mtiles;
        int w = ntiles - full;
        n = full + rem % w;
        m = rem / w;
    }
}

// ---------------- small kernels ----------------------------------------------
__global__ void zero_counters_kernel() {
    if (threadIdx.x < 2) g_count[threadIdx.x] = 0;
}

__global__ void route_gather_kernel(const float* __restrict__ x,
                                    const int* __restrict__ mask) {
    __shared__ int s_row;
    int t = blockIdx.x;
    if (threadIdx.x == 0) {
        int e = (mask[t] != 0) ? 1 : 0;
        int slot = atomicAdd(&g_count[e], 1);
        g_rowtok[e * NTOK + slot] = t;
        s_row = e * NTOK + slot;
    }
    __syncthreads();
    int row = s_row;
    const float4* src = reinterpret_cast<const float4*>(x + (size_t)t * DIM);
    __half2* dst = reinterpret_cast<__half2*>(g_xp + (size_t)row * DIM);
    for (int i = threadIdx.x; i < DIM / 4; i += blockDim.x) {
        float4 v = src[i];
        dst[2 * i + 0] = __floats2half2_rn(v.x, v.y);
        dst[2 * i + 1] = __floats2half2_rn(v.z, v.w);
    }
}

// fused fp32 -> fp16 convert of all three weight tensors (same layout)
#define NW4 ((int)(2 * (size_t)DIM * FFD / 4))
__global__ void convert_all_kernel(const float* __restrict__ wg,
                                   const float* __restrict__ wu,
                                   const float* __restrict__ wd) {
    int stride = gridDim.x * blockDim.x;
    for (int i = blockIdx.x * blockDim.x + threadIdx.x; i < 3 * NW4; i += stride) {
        int seg = i / NW4, rem = i - seg * NW4;
        const float* src = (seg == 0) ? wg : (seg == 1) ? wu : wd;
        __half* dst = (seg == 0) ? g_wgH : (seg == 1) ? g_wuH : g_wdH;
        float4 v = reinterpret_cast<const float4*>(src)[rem];
        __half2* d = reinterpret_cast<__half2*>(dst) + 2 * (size_t)rem;
        d[0] = __floats2half2_rn(v.x, v.y);
        d[1] = __floats2half2_rn(v.z, v.w);
    }
}

// ---------------- GEMM tiling ------------------------------------------------
// CTA tile 128(M) x 128(N). A: K-major smem rows (SRA=72 halves, BK=64).
// B: n-major smem rows (SRB=136 halves), ldmatrix.trans. 3-stage cp.async.
// GEMM1: 512 thr, 16 warps (4M x 4N), warp tile 32x32 -> 4 warps/SMSP.
// GEMM2: 256 thr, 8 warps (4M x 2N), warp tile 32x64, occ 2.
#define BM   128
#define BN   128
#define BK   64
#define SRA  72
#define SRB  136
#define STGA (BM * SRA)        // 9216 halves
#define STGB (BK * SRB)        // 8704 halves
#define STG1 (STGA + 2 * STGB) // gemm1 stage: 26624 halves = 53248 B
#define STG2 (STGA + STGB)     // gemm2 stage: 17920 halves = 35840 B
#define SMEM1 (3 * STG1 * 2)   // 159744 B
#define SMEM2 (3 * STG2 * 2)   // 107520 B

// ---------------- GEMM1: gate+up fused, h = silu(g)*u ------------------------
__global__ __launch_bounds__(512, 1) void gemm1_kernel() {
    extern __shared__ __half sm[];

    int tid = threadIdx.x, wid = tid >> 5, lane = tid & 31;
    int e = blockIdx.y, cnt = g_count[e];
    int mt_i, nt_i;
    tilemap(blockIdx.x, NTOK / BM, FFD / BN, mt_i, nt_i);
    int m0 = mt_i * BM;
    if (m0 >= cnt) return;
    int n0 = nt_i * BN;
    int wm = wid & 3, wn = wid >> 2;   // 4M x 4N warps, warp tile 32x32

    const __half* Ab = g_xp  + (size_t)(e * NTOK + m0) * DIM;
    const __half* Bg = g_wgH + (size_t)e * DIM * FFD + n0;
    const __half* Bu = g_wuH + (size_t)e * DIM * FFD + n0;
    uint32_t sbase = smem_to_u32(sm);

    float cg[2][4][4] = {}, cu[2][4][4] = {};

    int gq = lane >> 3, lr = lane & 7;
    int aRow = wm * 32 + lr + (gq & 1) * 8;            // + mt*16
    int aCol = (gq >> 1) * 8;                          // + ks*16
    uint32_t aoff = (uint32_t)(aRow * SRA + aCol) * 2;
    int bR = lr + (gq & 1) * 8;                        // k row, + ks*16
    int bC = wn * 32 + ((gq >> 1) & 1) * 8;            // n col, + j*16
    uint32_t boff = (uint32_t)(bR * SRB + bC) * 2;

    // loader: 3072 x 16B chunks (A 1024, Bg 1024, Bu 1024), 512 threads
    auto issue = [&](int it, int s) {
        uint32_t db = sbase + (uint32_t)(s * STG1) * 2;
        const __half* As = Ab + it * BK;
        const __half* Gs = Bg + (size_t)(it * BK) * FFD;
        const __half* Us = Bu + (size_t)(it * BK) * FFD;
        #pragma unroll
        for (int rep = 0; rep < 6; rep++) {
            int u = rep * 512 + tid;
            if (u < 1024) {
                int r = u >> 3, c = u & 7;
                cp16(db + (uint32_t)(r * SRA + c * 8) * 2,
                     As + (size_t)r * DIM + c * 8);
            } else if (u < 2048) {
                int v = u - 1024, r = v >> 4, c = v & 15;
                cp16(db + (uint32_t)(STGA + r * SRB + c * 8) * 2,
                     Gs + (size_t)r * FFD + c * 8);
            } else {
                int v = u - 2048, r = v >> 4, c = v & 15;
                cp16(db + (uint32_t)(STGA + STGB + r * SRB + c * 8) * 2,
                     Us + (size_t)r * FFD + c * 8);
            }
        }
    };

    issue(0, 0); CP_COMMIT();
    issue(1, 1); CP_COMMIT();

    const int KT = DIM / BK;  // 32
    for (int it = 0; it < KT; ++it) {
        CP_WAIT1();
        __syncthreads();
        if (it + 2 < KT) issue(it + 2, (it + 2) % 3);
        CP_COMMIT();

        uint32_t s0 = sbase + (uint32_t)((it % 3) * STG1) * 2;
        #pragma unroll
        for (int ks = 0; ks < 4; ++ks) {
            uint32_t a[2][4], b[2][4];
            #pragma unroll
            for (int mt = 0; mt < 2; ++mt)
                ldsm_x4(a[mt][0], a[mt][1], a[mt][2], a[mt][3],
                        s0 + aoff + (uint32_t)(mt * 16 * SRA + ks * 16) * 2);
            // gate
            uint32_t gb = s0 + (uint32_t)(STGA + ks * 16 * SRB) * 2 + boff;
            #pragma unroll
            for (int j = 0; j < 2; ++j)
                ldsm_x4t(b[j][0], b[j][1], b[j][2], b[j][3], gb + j * 32);
            #pragma unroll
            for (int mt = 0; mt < 2; ++mt)
                #pragma unroll
                for (int j = 0; j < 2; ++j) {
                    mma16816(cg[mt][j * 2 + 0], a[mt], b[j][0], b[j][1]);
                    mma16816(cg[mt][j * 2 + 1], a[mt], b[j][2], b[j][3]);
                }
            // up
            uint32_t ub = gb + (uint32_t)STGB * 2;
            #pragma unroll
            for (int j = 0; j < 2; ++j)
                ldsm_x4t(b[j][0], b[j][1], b[j][2], b[j][3], ub + j * 32);
            #pragma unroll
            for (int mt = 0; mt < 2; ++mt)
                #pragma unroll
                for (int j = 0; j < 2; ++j) {
                    mma16816(cu[mt][j * 2 + 0], a[mt], b[j][0], b[j][1]);
                    mma16816(cu[mt][j * 2 + 1], a[mt], b[j][2], b[j][3]);
                }
        }
    }

    // epilogue: h = silu(g)*u, fp16 half2 stores
    __half* hout = g_h + (size_t)(e * NTOK + m0) * FFD + n0;
    int rb = wm * 32 + (lane >> 2);
    int cb = wn * 32 + (lane & 3) * 2;
    #pragma unroll
    for (int mt = 0; mt < 2; ++mt)
        #pragma unroll
        for (int nt = 0; nt < 4; ++nt) {
            float* pg = cg[mt][nt];
            float* pu = cu[mt][nt];
            int r = rb + mt * 16, c = cb + nt * 8;
            *reinterpret_cast<__half2*>(hout + (size_t)r * FFD + c) =
                __floats2half2_rn(silu(pg[0]) * pu[0], silu(pg[1]) * pu[1]);
            *reinterpret_cast<__half2*>(hout + (size_t)(r + 8) * FFD + c) =
                __floats2half2_rn(silu(pg[2]) * pu[2], silu(pg[3]) * pu[3]);
        }
}

// ---------------- GEMM2: out = h @ Wd, scattered to token order --------------
__global__ __launch_bounds__(256, 2) void gemm2_kernel(float* __restrict__ out) {
    extern __shared__ __half sm[];
    __shared__ int srt[BM];

    int tid = threadIdx.x, wid = tid >> 5, lane = tid & 31;
    int e = blockIdx.y, cnt = g_count[e];
    int mt_i, nt_i;
    tilemap(blockIdx.x, NTOK / BM, DIM / BN, mt_i, nt_i);
    int m0 = mt_i * BM;
    if (m0 >= cnt) return;
    int n0 = nt_i * BN;
    int wm = wid & 3, wn = wid >> 2;   // 4M x 2N warps, warp tile 32x64

    for (int i = tid; i < BM; i += 256) {
        int rr = m0 + i;
        srt[i] = (rr < cnt) ? g_rowtok[e * NTOK + rr] : -1;
    }

    const __half* Ab = g_h   + (size_t)(e * NTOK + m0) * FFD;
    const __half* Bb = g_wdH + (size_t)e * FFD * DIM + n0;
    uint32_t sbase = smem_to_u32(sm);

    float cc[2][8][4] = {};

    int gq = lane >> 3, lr = lane & 7;
    int aRow = wm * 32 + lr + (gq & 1) * 8;
    int aCol = (gq >> 1) * 8;
    uint32_t aoff = (uint32_t)(aRow * SRA + aCol) * 2;
    int bR = lr + (gq & 1) * 8;
    int bC = wn * 64 + ((gq >> 1) & 1) * 8;
    uint32_t boff = (uint32_t)(bR * SRB + bC) * 2;

    // loader: 2048 x 16B chunks (A 1024, B 1024), 256 threads
    auto issue = [&](int it, int s) {
        uint32_t db = sbase + (uint32_t)(s * STG2) * 2;
        const __half* As = Ab + it * BK;
        const __half* Bs = Bb + (size_t)(it * BK) * DIM;
        #pragma unroll
        for (int rep = 0; rep < 8; rep++) {
            int u = rep * 256 + tid;
            if (u < 1024) {
                int r = u >> 3, c = u & 7;
                cp16(db + (uint32_t)(r * SRA + c * 8) * 2,
                     As + (size_t)r * FFD + c * 8);
            } else {
                int v = u - 1024, r = v >> 4, c = v & 15;
                cp16(db + (uint32_t)(STGA + r * SRB + c * 8) * 2,
                     Bs + (size_t)r * DIM + c * 8);
            }
        }
    };

    issue(0, 0); CP_COMMIT();
    issue(1, 1); CP_COMMIT();

    const int KT = FFD / BK;  // 88
    for (int it = 0; it < KT; ++it) {
        CP_WAIT1();
        __syncthreads();
        if (it + 2 < KT) issue(it + 2, (it + 2) % 3);
        CP_COMMIT();

        uint32_t s0 = sbase + (uint32_t)((it % 3) * STG2) * 2;
        #pragma unroll
        for (int ks = 0; ks < 4; ++ks) {
            uint32_t a[2][4], b[4][4];
            #pragma unroll
            for (int mt = 0; mt < 2; ++mt)
                ldsm_x4(a[mt][0], a[mt][1], a[mt][2], a[mt][3],
                        s0 + aoff + (uint32_t)(mt * 16 * SRA + ks * 16) * 2);
            uint32_t bb = s0 + (uint32_t)(STGA + ks * 16 * SRB) * 2 + boff;
            #pragma unroll
            for (int j = 0; j < 4; ++j)
                ldsm_x4t(b[j][0], b[j][1], b[j][2], b[j][3], bb + j * 32);
            #pragma unroll
            for (int mt = 0; mt < 2; ++mt)
                #pragma unroll
                for (int j = 0; j < 4; ++j) {
                    mma16816(cc[mt][j * 2 + 0], a[mt], b[j][0], b[j][1]);
                    mma16816(cc[mt][j * 2 + 1], a[mt], b[j][2], b[j][3]);
                }
        }
    }

    // epilogue: scatter rows to original token positions (fp32 float2)
    int rb = wm * 32 + (lane >> 2);
    int cb = n0 + wn * 64 + (lane & 3) * 2;
    #pragma unroll
    for (int mt = 0; mt < 2; ++mt)
        #pragma unroll
        for (int nt = 0; nt < 8; ++nt) {
            float* p = cc[mt][nt];
            int rl = rb + mt * 16;
            int c = cb + nt * 8;
            int t0 = srt[rl];
            if (t0 >= 0)
                *reinterpret_cast<float2*>(out + (size_t)t0 * DIM + c) =
                    make_float2(p[0], p[1]);
            int t1 = srt[rl + 8];
            if (t1 >= 0)
                *reinterpret_cast<float2*>(out + (size_t)t1 * DIM + c) =
                    make_float2(p[2], p[3]);
        }
}

// ---------------- launch ------------------------------------------------------
extern "C" void kernel_launch(void* const* d_in, const int* in_sizes, int n_in,
                              void* d_out, int out_size) {
    const float* hs   = (const float*)d_in[0];
    const int*   mask = (const int*)d_in[1];
    const float* wg   = (const float*)d_in[2];
    const float* wu   = (const float*)d_in[3];
    const float* wd   = (const float*)d_in[4];
    float* out = (float*)d_out;
    (void)in_sizes; (void)n_in; (void)out_size;

    cudaFuncSetAttribute(gemm1_kernel,
                         cudaFuncAttributeMaxDynamicSharedMemorySize, SMEM1);
    cudaFuncSetAttribute(gemm2_kernel,
                         cudaFuncAttributeMaxDynamicSharedMemorySize, SMEM2);

    zero_counters_kernel<<<1, 32>>>();
    route_gather_kernel<<<NTOK, 128>>>(hs, mask);
    convert_all_kernel<<<8192, 256>>>(wg, wu, wd);

    dim3 g1((NTOK / BM) * (FFD / BN), 2);
    gemm1_kernel<<<g1, 512, SMEM1>>>();

    dim3 g2((NTOK / BM) * (DIM / BN), 2);
    gemm2_kernel<<<g2, 256, SMEM2>>>(out);
}